// round 11
// baseline (speedup 1.0000x reference)
#include <cuda_runtime.h>
#include <math.h>

#define DDIM 512        // feature dim per row
#define GROUPS 128      // groups per row (one row per block)
#define KCODES 1024
#define NQUADS 256
#define NTHREADS 256    // 8 warps = 2 K-chunks x 4 group-sets
#define NWARPS 8
#define QCHUNK 128      // quads per K-chunk
#define IDXMASK 0x3FFu
#define PACKMASK 0xFFFFFC00u      // 10-bit (code) pack
#define QIDXMASK 0xFFu
#define QPACKMASK 0xFFFFFF00u     // 8-bit (quad) pack

__device__ float g_partials[512];
__device__ int   g_count = 0;

__global__ void __launch_bounds__(NTHREADS) vq_fused_kernel(
    const float* __restrict__ fb,
    const float* __restrict__ emb,
    float* __restrict__ out,
    int n_elems, int nblocks, int out_size)
{
    __shared__ float4 s_code[KCODES];     // 16 KB
    __shared__ float  s_nh[KCODES];       // -0.5*||e||^2, 4 KB
    __shared__ float  s_row[DDIM];        // 2 KB
    __shared__ float  s_m[GROUPS * 2];    // packed per-(group,chunk) best, 1 KB
    __shared__ float  s_red[NWARPS];
    __shared__ float  s_scale[2];
    __shared__ bool   s_last;

    const int tid = threadIdx.x;
    const int row = blockIdx.x;
    const float* x = fb + (size_t)row * DDIM;

    // ---- load codebook into smem, precompute -0.5*||e||^2 ----
    #pragma unroll
    for (int k = tid; k < KCODES; k += NTHREADS) {
        float4 e = reinterpret_cast<const float4*>(emb)[k];
        s_code[k] = e;
        s_nh[k] = -0.5f * (e.x*e.x + e.y*e.y + e.z*e.z + e.w*e.w);
    }

    // ---- load row, sum of squares ----
    float ss = 0.0f;
    #pragma unroll
    for (int j = tid; j < DDIM; j += NTHREADS) {
        float v = x[j];
        s_row[j] = v;
        ss = fmaf(v, v, ss);
    }
    #pragma unroll
    for (int o = 16; o > 0; o >>= 1)
        ss += __shfl_xor_sync(0xffffffffu, ss, o);
    if ((tid & 31) == 0) s_red[tid >> 5] = ss;
    __syncthreads();

    if (tid == 0) {
        float tot = 0.0f;
        #pragma unroll
        for (int w = 0; w < NWARPS; w++) tot += s_red[w];
        float scale = sqrtf(tot);
        // FloatBiter (faithful fp32)
        float xc = fminf(fmaxf(scale + 1.0f, 1.0f), 16.0f);
        float lg = logf(xc) / 1.3862943611198906f;
        float s = 0.0f;
        #pragma unroll
        for (int i = 0; i < 8; i++) {
            float base = (float)(1 << i);
            int bit = ((int)floorf(lg * base)) & 1;
            s += (float)bit / base;
        }
        s_scale[0] = scale;
        s_scale[1] = powf(4.0f, s) - 1.0f;
    }
    __syncthreads();

    const float scale = s_scale[0];

    // ---- argmax of m_k = fn.e_k - 0.5||e_k||^2 over codes ----
    // GROUP-PER-LANE: warp = (kchunk, groupset); lane owns ONE group and
    // scans 128 quads. Codebook LDS broadcasts now serve 32 groups per warp.
    const int lane = tid & 31;
    const int wid = tid >> 5;
    const int kc = wid >> 2;              // K-chunk (0/1)
    const int gs = wid & 3;               // group-set (0..3)
    const int g = gs * 32 + lane;         // this lane's group (0..127)

    float xr[4];
    {
        float4 r4 = reinterpret_cast<const float4*>(s_row)[g];  // LDS.128, no conflict
        xr[0] = r4.x / scale;   // IEEE div == fn
        xr[1] = r4.y / scale;
        xr[2] = r4.z / scale;
        xr[3] = r4.w / scale;
    }

    float best = -3e38f;
    const int qbeg = kc * QCHUNK;

    #pragma unroll 2
    for (int q = qbeg; q < qbeg + QCHUNK; q++) {
        float4 nh4 = *reinterpret_cast<const float4*>(&s_nh[4 * q]);  // LDS.128 bcast
        float4 c0 = s_code[4 * q + 0];    // warp-uniform -> broadcast LDS.128
        float4 c1 = s_code[4 * q + 1];
        float4 c2 = s_code[4 * q + 2];
        float4 c3 = s_code[4 * q + 3];
        float m0 = fmaf(xr[3], c0.w, fmaf(xr[2], c0.z,
                   fmaf(xr[1], c0.y, fmaf(xr[0], c0.x, nh4.x))));
        float m1 = fmaf(xr[3], c1.w, fmaf(xr[2], c1.z,
                   fmaf(xr[1], c1.y, fmaf(xr[0], c1.x, nh4.y))));
        float m2 = fmaf(xr[3], c2.w, fmaf(xr[2], c2.z,
                   fmaf(xr[1], c2.y, fmaf(xr[0], c2.x, nh4.z))));
        float m3 = fmaf(xr[3], c3.w, fmaf(xr[2], c3.z,
                   fmaf(xr[1], c3.y, fmaf(xr[0], c3.x, nh4.w))));
        float t = fmaxf(fmaxf(m0, m1), fmaxf(m2, m3));   // 2-level tree
        float pk = __uint_as_float((__float_as_uint(t) & QPACKMASK) | (unsigned)q);
        best = fmaxf(best, pk);
    }

    // ---- fix-up: rescan winning quad at 10-bit code precision ----
    {
        const int bq = (int)(__float_as_uint(best) & QIDXMASK);
        float4 nh4 = *reinterpret_cast<const float4*>(&s_nh[4 * bq]);
        const float nh[4] = {nh4.x, nh4.y, nh4.z, nh4.w};
        float fix = -3e38f;
        #pragma unroll
        for (int u = 0; u < 4; u++) {
            const int k = 4 * bq + u;
            float4 c = s_code[k];
            float m = fmaf(xr[3], c.w, fmaf(xr[2], c.z,
                      fmaf(xr[1], c.y, fmaf(xr[0], c.x, nh[u]))));
            float pk = __uint_as_float((__float_as_uint(m) & PACKMASK) | (unsigned)k);
            fix = fmaxf(fix, pk);
        }
        s_m[g * 2 + kc] = fix;
    }
    __syncthreads();

    // ---- combine 2 K-chunk partials: one group per thread (first 128) ----
    float l = 0.0f;
    if (tid < GROUPS) {
        const int gg = tid;
        float bm = fmaxf(s_m[gg * 2 + 0], s_m[gg * 2 + 1]);
        const int bx = (int)(__float_as_uint(bm) & IDXMASK);

        float4 e = s_code[bx];
        const float sq = s_scale[1];
        reinterpret_cast<float4*>(out + (size_t)row * DDIM)[gg] =
            make_float4(e.x * sq, e.y * sq, e.z * sq, e.w * sq);

        // loss: sum (fqn - fn)^2 (full-precision e, recomputed fn)
        float d0 = e.x - s_row[gg * 4 + 0] / scale;
        float d1 = e.y - s_row[gg * 4 + 1] / scale;
        float d2 = e.z - s_row[gg * 4 + 2] / scale;
        float d3 = e.w - s_row[gg * 4 + 3] / scale;
        l = d0*d0 + d1*d1 + d2*d2 + d3*d3;
    }
    // reduce l (threads >= 128 contribute 0)
    #pragma unroll
    for (int o = 16; o > 0; o >>= 1)
        l += __shfl_xor_sync(0xffffffffu, l, o);
    __syncthreads();   // s_red reuse
    if ((tid & 31) == 0) s_red[tid >> 5] = l;
    __syncthreads();

    // ---- last-block fused loss reduction (deterministic fixed order) ----
    if (tid == 0) {
        g_partials[row] = s_red[0] + s_red[1] + s_red[2] + s_red[3];
        __threadfence();
        int prev = atomicAdd(&g_count, 1);
        s_last = (prev == nblocks - 1);
    }
    __syncthreads();

    if (s_last && tid < 128) {
        __threadfence();
        float v = g_partials[tid] + g_partials[tid + 128]
                + g_partials[tid + 256] + g_partials[tid + 384];
        #pragma unroll
        for (int o = 16; o > 0; o >>= 1)
            v += __shfl_xor_sync(0xffffffffu, v, o);
        if ((tid & 31) == 0) s_red[tid >> 5] = v;
    }
    __syncthreads();
    if (s_last && tid == 0) {
        float loss = (s_red[0] + s_red[1] + s_red[2] + s_red[3]) / (float)n_elems;
        if (out_size >= n_elems + 1) out[n_elems] = loss;
        if (out_size >= n_elems + 2) out[n_elems + 1] = loss;
        g_count = 0;   // reset for next replay
    }
}

extern "C" void kernel_launch(void* const* d_in, const int* in_sizes, int n_in,
                              void* d_out, int out_size)
{
    const float* fb  = (const float*)d_in[0];
    const float* emb = (const float*)d_in[1];
    float* out = (float*)d_out;

    int n = in_sizes[0];       // 262144
    int rows = n / DDIM;       // 512

    vq_fused_kernel<<<rows, NTHREADS>>>(fb, emb, out, n, rows, out_size);
}

// round 12
// speedup vs baseline: 1.0801x; 1.0801x over previous
#include <cuda_runtime.h>
#include <math.h>

#define DDIM 512        // feature dim per row
#define GROUPS 128      // groups per row (one full row per block)
#define KCODES 1024
#define NTHREADS 256    // 8 warps
#define NWARPS 8
#define QCHUNK 32       // quads per warp chunk (8 warps x 32 quads = 1024 codes)
#define IDXMASK 0x3FFu
#define PACKMASK 0xFFFFFC00u      // 10-bit (code) pack
#define QIDXMASK 0xFFu
#define QPACKMASK 0xFFFFFF00u     // 8-bit (quad) pack

__device__ float g_partials[512];
__device__ int   g_count = 0;

__global__ void __launch_bounds__(NTHREADS) vq_fused_kernel(
    const float* __restrict__ fb,
    const float* __restrict__ emb,
    float* __restrict__ out,
    int n_elems, int nblocks, int out_size)
{
    __shared__ float4 s_code[KCODES];       // 16 KB
    __shared__ float  s_nh[KCODES];         // -0.5*||e||^2, 4 KB
    __shared__ float  s_row[DDIM];          // 2 KB
    __shared__ float  s_m[GROUPS * NWARPS]; // packed per-(group,chunk) best, 4 KB
    __shared__ float  s_red[NWARPS];
    __shared__ float  s_scale[2];
    __shared__ bool   s_last;

    const int tid = threadIdx.x;
    const int row = blockIdx.x;
    const float* x = fb + (size_t)row * DDIM;

    // ---- load codebook into smem, precompute -0.5*||e||^2 ----
    #pragma unroll
    for (int k = tid; k < KCODES; k += NTHREADS) {
        float4 e = reinterpret_cast<const float4*>(emb)[k];
        s_code[k] = e;
        s_nh[k] = -0.5f * (e.x*e.x + e.y*e.y + e.z*e.z + e.w*e.w);
    }

    // ---- load row, sum of squares ----
    float ss = 0.0f;
    #pragma unroll
    for (int j = tid; j < DDIM; j += NTHREADS) {
        float v = x[j];
        s_row[j] = v;
        ss = fmaf(v, v, ss);
    }
    #pragma unroll
    for (int o = 16; o > 0; o >>= 1)
        ss += __shfl_xor_sync(0xffffffffu, ss, o);
    if ((tid & 31) == 0) s_red[tid >> 5] = ss;
    __syncthreads();

    if (tid == 0) {
        float tot = 0.0f;
        #pragma unroll
        for (int w = 0; w < NWARPS; w++) tot += s_red[w];
        float scale = sqrtf(tot);
        // FloatBiter (faithful fp32)
        float xc = fminf(fmaxf(scale + 1.0f, 1.0f), 16.0f);
        float lg = logf(xc) / 1.3862943611198906f;
        float s = 0.0f;
        #pragma unroll
        for (int i = 0; i < 8; i++) {
            float base = (float)(1 << i);
            int bit = ((int)floorf(lg * base)) & 1;
            s += (float)bit / base;
        }
        s_scale[0] = scale;
        s_scale[1] = powf(4.0f, s) - 1.0f;
    }
    __syncthreads();

    const float scale = s_scale[0];

    // ---- argmax of m_k = fn.e_k - 0.5||e_k||^2 over codes ----
    // 32 lanes x 4 groups = 128 groups per warp (= full row); 8 warps each
    // scan a 32-quad chunk. Each LDS broadcast serves 128 group-dots.
    // Quad tournament (proven R10): 3-FMNMX tree, 8-bit quad id in mantissa,
    // one FMNMX vs running best; winning quad rescanned at 10-bit precision.
    const int gslot = tid & 31;
    const int kc = tid >> 5;              // warp id = K-chunk (0..7)
    const int g0 = gslot * 4;             // this lane's 4 groups

    float xr[4][4];
    #pragma unroll
    for (int gg = 0; gg < 4; gg++) {
        float4 r4 = reinterpret_cast<const float4*>(s_row)[g0 + gg];
        xr[gg][0] = r4.x / scale;   // IEEE div == fn
        xr[gg][1] = r4.y / scale;
        xr[gg][2] = r4.z / scale;
        xr[gg][3] = r4.w / scale;
    }

    float best[4] = {-3e38f, -3e38f, -3e38f, -3e38f};
    const int qbeg = kc * QCHUNK;

    #pragma unroll 2
    for (int q = qbeg; q < qbeg + QCHUNK; q++) {
        float4 nh4 = *reinterpret_cast<const float4*>(&s_nh[4 * q]);  // LDS.128 bcast
        float4 c0 = s_code[4 * q + 0];    // warp-uniform -> broadcast LDS.128
        float4 c1 = s_code[4 * q + 1];
        float4 c2 = s_code[4 * q + 2];
        float4 c3 = s_code[4 * q + 3];
        #pragma unroll
        for (int gg = 0; gg < 4; gg++) {
            float m0 = fmaf(xr[gg][3], c0.w, fmaf(xr[gg][2], c0.z,
                       fmaf(xr[gg][1], c0.y, fmaf(xr[gg][0], c0.x, nh4.x))));
            float m1 = fmaf(xr[gg][3], c1.w, fmaf(xr[gg][2], c1.z,
                       fmaf(xr[gg][1], c1.y, fmaf(xr[gg][0], c1.x, nh4.y))));
            float m2 = fmaf(xr[gg][3], c2.w, fmaf(xr[gg][2], c2.z,
                       fmaf(xr[gg][1], c2.y, fmaf(xr[gg][0], c2.x, nh4.z))));
            float m3 = fmaf(xr[gg][3], c3.w, fmaf(xr[gg][2], c3.z,
                       fmaf(xr[gg][1], c3.y, fmaf(xr[gg][0], c3.x, nh4.w))));
            float t = fmaxf(fmaxf(m0, m1), fmaxf(m2, m3));   // 2-level tree
            float pk = __uint_as_float((__float_as_uint(t) & QPACKMASK) | (unsigned)q);
            best[gg] = fmaxf(best[gg], pk);
        }
    }

    // ---- fix-up: rescan winning quad at 10-bit code precision ----
    #pragma unroll
    for (int gg = 0; gg < 4; gg++) {
        const int bq = (int)(__float_as_uint(best[gg]) & QIDXMASK);
        float4 nh4 = *reinterpret_cast<const float4*>(&s_nh[4 * bq]);
        const float nh[4] = {nh4.x, nh4.y, nh4.z, nh4.w};
        float fix = -3e38f;
        #pragma unroll
        for (int u = 0; u < 4; u++) {
            const int k = 4 * bq + u;
            float4 c = s_code[k];
            float m = fmaf(xr[gg][3], c.w, fmaf(xr[gg][2], c.z,
                      fmaf(xr[gg][1], c.y, fmaf(xr[gg][0], c.x, nh[u]))));
            float pk = __uint_as_float((__float_as_uint(m) & PACKMASK) | (unsigned)k);
            fix = fmaxf(fix, pk);
        }
        s_m[(g0 + gg) * NWARPS + kc] = fix;
    }
    __syncthreads();

    // ---- combine 8 chunk partials: one group per thread (first 128) ----
    float l = 0.0f;
    if (tid < GROUPS) {
        const int g = tid;
        float bm = s_m[g * NWARPS];
        #pragma unroll
        for (int c = 1; c < NWARPS; c++)
            bm = fmaxf(bm, s_m[g * NWARPS + c]);
        const int bx = (int)(__float_as_uint(bm) & IDXMASK);

        float4 e = s_code[bx];
        const float sq = s_scale[1];
        reinterpret_cast<float4*>(out + (size_t)row * DDIM)[g] =
            make_float4(e.x * sq, e.y * sq, e.z * sq, e.w * sq);

        // loss: sum (fqn - fn)^2 (full-precision e, recomputed fn)
        float d0 = e.x - s_row[g * 4 + 0] / scale;
        float d1 = e.y - s_row[g * 4 + 1] / scale;
        float d2 = e.z - s_row[g * 4 + 2] / scale;
        float d3 = e.w - s_row[g * 4 + 3] / scale;
        l = d0*d0 + d1*d1 + d2*d2 + d3*d3;
    }
    // reduce l (threads >= 128 contribute 0)
    #pragma unroll
    for (int o = 16; o > 0; o >>= 1)
        l += __shfl_xor_sync(0xffffffffu, l, o);
    __syncthreads();   // s_red reuse
    if ((tid & 31) == 0) s_red[tid >> 5] = l;
    __syncthreads();

    // ---- last-block fused loss reduction (deterministic fixed order) ----
    if (tid == 0) {
        g_partials[row] = s_red[0] + s_red[1] + s_red[2] + s_red[3];
        __threadfence();
        int prev = atomicAdd(&g_count, 1);
        s_last = (prev == nblocks - 1);
    }
    __syncthreads();

    if (s_last && tid < 128) {
        __threadfence();
        float v = g_partials[tid] + g_partials[tid + 128]
                + g_partials[tid + 256] + g_partials[tid + 384];
        #pragma unroll
        for (int o = 16; o > 0; o >>= 1)
            v += __shfl_xor_sync(0xffffffffu, v, o);
        if ((tid & 31) == 0) s_red[tid >> 5] = v;
    }
    __syncthreads();
    if (s_last && tid == 0) {
        float loss = (s_red[0] + s_red[1] + s_red[2] + s_red[3]) / (float)n_elems;
        if (out_size >= n_elems + 1) out[n_elems] = loss;
        if (out_size >= n_elems + 2) out[n_elems + 1] = loss;
        g_count = 0;   // reset for next replay
    }
}

extern "C" void kernel_launch(void* const* d_in, const int* in_sizes, int n_in,
                              void* d_out, int out_size)
{
    const float* fb  = (const float*)d_in[0];
    const float* emb = (const float*)d_in[1];
    float* out = (float*)d_out;

    int n = in_sizes[0];       // 262144
    int rows = n / DDIM;       // 512

    vq_fused_kernel<<<rows, NTHREADS>>>(fb, emb, out, n, rows, out_size);
}

// round 13
// speedup vs baseline: 1.2424x; 1.1503x over previous
#include <cuda_runtime.h>
#include <math.h>

#define DDIM 512        // feature dim per row
#define GROUPS 128      // groups per row
#define KCODES 1024
#define NTHREADS 128    // 4 warps
#define NWARPS 4
#define QCHUNK 32       // quads per warp (4 warps x 32 quads = 512 codes = half)
#define ROWS 512
#define IDXMASK 0x3FFu
#define PACKMASK 0xFFFFFC00u      // 10-bit (code) pack
#define QIDXMASK 0xFFu
#define QPACKMASK 0xFFFFFF00u     // 8-bit (quad) pack

__device__ float g_rowbuf[ROWS * 2 * GROUPS];   // per (row, khalf, group) packed best
__device__ int   g_rowcnt[ROWS];                // per-row arrival counter
__device__ float g_partials[ROWS];              // per-row loss partials
__device__ int   g_count = 0;

__global__ void __launch_bounds__(NTHREADS) vq_fused_kernel(
    const float* __restrict__ fb,
    const float* __restrict__ emb,
    float* __restrict__ out,
    int n_elems, int rows, int out_size)
{
    __shared__ float4 s_code[KCODES];       // 16 KB (full codebook: combine needs any e[bx])
    __shared__ float  s_nh[KCODES];         // 4 KB
    __shared__ float  s_row[DDIM];          // 2 KB
    __shared__ float  s_m[GROUPS * NWARPS]; // packed per-(group,warp) best, 2 KB
    __shared__ float  s_red[NWARPS];
    __shared__ float  s_scale[2];
    __shared__ bool   s_second;
    __shared__ bool   s_last;

    const int tid = threadIdx.x;
    const int row = blockIdx.x >> 1;
    const int kh  = blockIdx.x & 1;        // codebook half this block scans
    const float* x = fb + (size_t)row * DDIM;

    // ---- load full codebook into smem, precompute -0.5*||e||^2 ----
    #pragma unroll
    for (int k = tid; k < KCODES; k += NTHREADS) {
        float4 e = reinterpret_cast<const float4*>(emb)[k];
        s_code[k] = e;
        s_nh[k] = -0.5f * (e.x*e.x + e.y*e.y + e.z*e.z + e.w*e.w);
    }

    // ---- load row, sum of squares ----
    float ss = 0.0f;
    #pragma unroll
    for (int j = tid; j < DDIM; j += NTHREADS) {
        float v = x[j];
        s_row[j] = v;
        ss = fmaf(v, v, ss);
    }
    #pragma unroll
    for (int o = 16; o > 0; o >>= 1)
        ss += __shfl_xor_sync(0xffffffffu, ss, o);
    if ((tid & 31) == 0) s_red[tid >> 5] = ss;
    __syncthreads();

    if (tid == 0) {
        float tot = s_red[0] + s_red[1] + s_red[2] + s_red[3];
        float scale = sqrtf(tot);
        // FloatBiter (faithful fp32)
        float xc = fminf(fmaxf(scale + 1.0f, 1.0f), 16.0f);
        float lg = logf(xc) / 1.3862943611198906f;
        float s = 0.0f;
        #pragma unroll
        for (int i = 0; i < 8; i++) {
            float base = (float)(1 << i);
            int bit = ((int)floorf(lg * base)) & 1;
            s += (float)bit / base;
        }
        s_scale[0] = scale;
        s_scale[1] = powf(4.0f, s) - 1.0f;
    }
    __syncthreads();

    const float scale = s_scale[0];

    // ---- argmax of m_k = fn.e_k - 0.5||e_k||^2 over this block's 512 codes ----
    // 32 lanes x 4 groups = 128 groups per warp; 4 warps x 32-quad chunks.
    // Quad tournament: FMNMX tree + 8-bit quad pack; winning quad rescanned.
    const int gslot = tid & 31;
    const int kc = tid >> 5;               // warp id = chunk within half (0..3)
    const int g0 = gslot * 4;              // this lane's 4 groups

    float xr[4][4];
    #pragma unroll
    for (int gg = 0; gg < 4; gg++) {
        float4 r4 = reinterpret_cast<const float4*>(s_row)[g0 + gg];
        xr[gg][0] = r4.x / scale;   // IEEE div == fn
        xr[gg][1] = r4.y / scale;
        xr[gg][2] = r4.z / scale;
        xr[gg][3] = r4.w / scale;
    }

    float best[4] = {-3e38f, -3e38f, -3e38f, -3e38f};
    const int qbeg = kh * 128 + kc * QCHUNK;   // quad index (0..255)

    #pragma unroll 2
    for (int q = qbeg; q < qbeg + QCHUNK; q++) {
        float4 nh4 = *reinterpret_cast<const float4*>(&s_nh[4 * q]);  // LDS.128 bcast
        float4 c0 = s_code[4 * q + 0];     // warp-uniform -> broadcast LDS.128
        float4 c1 = s_code[4 * q + 1];
        float4 c2 = s_code[4 * q + 2];
        float4 c3 = s_code[4 * q + 3];
        #pragma unroll
        for (int gg = 0; gg < 4; gg++) {
            float m0 = fmaf(xr[gg][3], c0.w, fmaf(xr[gg][2], c0.z,
                       fmaf(xr[gg][1], c0.y, fmaf(xr[gg][0], c0.x, nh4.x))));
            float m1 = fmaf(xr[gg][3], c1.w, fmaf(xr[gg][2], c1.z,
                       fmaf(xr[gg][1], c1.y, fmaf(xr[gg][0], c1.x, nh4.y))));
            float m2 = fmaf(xr[gg][3], c2.w, fmaf(xr[gg][2], c2.z,
                       fmaf(xr[gg][1], c2.y, fmaf(xr[gg][0], c2.x, nh4.z))));
            float m3 = fmaf(xr[gg][3], c3.w, fmaf(xr[gg][2], c3.z,
                       fmaf(xr[gg][1], c3.y, fmaf(xr[gg][0], c3.x, nh4.w))));
            float t = fmaxf(fmaxf(m0, m1), fmaxf(m2, m3));   // 2-level tree
            float pk = __uint_as_float((__float_as_uint(t) & QPACKMASK) | (unsigned)q);
            best[gg] = fmaxf(best[gg], pk);
        }
    }

    // ---- fix-up: rescan winning quad at 10-bit code precision ----
    #pragma unroll
    for (int gg = 0; gg < 4; gg++) {
        const int bq = (int)(__float_as_uint(best[gg]) & QIDXMASK);
        float4 nh4 = *reinterpret_cast<const float4*>(&s_nh[4 * bq]);
        const float nh[4] = {nh4.x, nh4.y, nh4.z, nh4.w};
        float fix = -3e38f;
        #pragma unroll
        for (int u = 0; u < 4; u++) {
            const int k = 4 * bq + u;
            float4 c = s_code[k];
            float m = fmaf(xr[gg][3], c.w, fmaf(xr[gg][2], c.z,
                      fmaf(xr[gg][1], c.y, fmaf(xr[gg][0], c.x, nh[u]))));
            float pk = __uint_as_float((__float_as_uint(m) & PACKMASK) | (unsigned)k);
            fix = fmaxf(fix, pk);
        }
        s_m[(g0 + gg) * NWARPS + kc] = fix;
    }
    __syncthreads();

    // ---- local combine (4 warps) + publish this half's result ----
    // one group per thread: tid == group (0..127)
    {
        const int g = tid;
        float bm = fmaxf(fmaxf(s_m[g * NWARPS + 0], s_m[g * NWARPS + 1]),
                         fmaxf(s_m[g * NWARPS + 2], s_m[g * NWARPS + 3]));
        g_rowbuf[((size_t)row * 2 + kh) * GROUPS + g] = bm;
    }
    __syncthreads();
    if (tid == 0) {
        __threadfence();
        int prev = atomicAdd(&g_rowcnt[row], 1);
        s_second = (prev == 1);
    }
    __syncthreads();
    if (!s_second) return;     // first arrival: other block finishes the row

    // ---- second arrival: combine both halves, write output + row loss ----
    __threadfence();
    float l = 0.0f;
    {
        const int g = tid;
        float a = g_rowbuf[((size_t)row * 2 + 0) * GROUPS + g];
        float b = g_rowbuf[((size_t)row * 2 + 1) * GROUPS + g];
        float bm = fmaxf(a, b);
        const int bx = (int)(__float_as_uint(bm) & IDXMASK);

        float4 e = s_code[bx];
        const float sq = s_scale[1];
        reinterpret_cast<float4*>(out + (size_t)row * DDIM)[g] =
            make_float4(e.x * sq, e.y * sq, e.z * sq, e.w * sq);

        // loss: sum (fqn - fn)^2 (full-precision e, recomputed fn)
        float d0 = e.x - s_row[g * 4 + 0] / scale;
        float d1 = e.y - s_row[g * 4 + 1] / scale;
        float d2 = e.z - s_row[g * 4 + 2] / scale;
        float d3 = e.w - s_row[g * 4 + 3] / scale;
        l = d0*d0 + d1*d1 + d2*d2 + d3*d3;
    }
    #pragma unroll
    for (int o = 16; o > 0; o >>= 1)
        l += __shfl_xor_sync(0xffffffffu, l, o);
    if ((tid & 31) == 0) s_red[tid >> 5] = l;
    __syncthreads();

    if (tid == 0) {
        g_rowcnt[row] = 0;      // reset for next graph replay
        g_partials[row] = s_red[0] + s_red[1] + s_red[2] + s_red[3];
        __threadfence();
        int prev = atomicAdd(&g_count, 1);
        s_last = (prev == rows - 1);
    }
    __syncthreads();

    if (s_last) {
        __threadfence();
        float v = g_partials[tid] + g_partials[tid + 128]
                + g_partials[tid + 256] + g_partials[tid + 384];
        #pragma unroll
        for (int o = 16; o > 0; o >>= 1)
            v += __shfl_xor_sync(0xffffffffu, v, o);
        __syncthreads();
        if ((tid & 31) == 0) s_red[tid >> 5] = v;
        __syncthreads();
        if (tid == 0) {
            float loss = (s_red[0] + s_red[1] + s_red[2] + s_red[3]) / (float)n_elems;
            if (out_size >= n_elems + 1) out[n_elems] = loss;
            if (out_size >= n_elems + 2) out[n_elems + 1] = loss;
            g_count = 0;        // reset for next replay
        }
    }
}

extern "C" void kernel_launch(void* const* d_in, const int* in_sizes, int n_in,
                              void* d_out, int out_size)
{
    const float* fb  = (const float*)d_in[0];
    const float* emb = (const float*)d_in[1];
    float* out = (float*)d_out;

    int n = in_sizes[0];       // 262144
    int rows = n / DDIM;       // 512
    int nblocks = rows * 2;    // 1024 = (row, codebook-half)

    vq_fused_kernel<<<nblocks, NTHREADS>>>(fb, emb, out, n, rows, out_size);
}